// round 5
// baseline (speedup 1.0000x reference)
#include <cuda_runtime.h>
#include <cuda_bf16.h>
#include <math.h>

// ---------------------------------------------------------------------------
// HierarchicalClustering via split-bf16 tensor-core GEMMs (mma.sync HMMA).
//   logits = 0.5*(h @ c^T) - 0.25*||c||^2   (||h||^2 cancels in softmax)
//   p      = softmax_rows(logits)
//   t      = tanh(h @ W^T + b)
//   h_next = p^T @ t
// GEMM: C = A @ B^T, A,B as bf16 (hi,lo) pair-packed arrays [rows][K/2]
// (u32 = {bf16 even-k, bf16 odd-k}), computed hi*hi + hi*lo + lo*hi, fp32 acc.
// 128x128 CTA tile, 4 warps of 64x64 (2 CTAs/SM), ldmatrix operand loads.
// Level-1 p^T@t uses split-K=2 + add-reduce.
// ---------------------------------------------------------------------------

#define D 1024
#define N0 16384
#define N1 2048
#define N2 256
#define N3 32

// ------------------------- scratch (device globals) ------------------------
__device__ float    g_G[(size_t)N0 * N1];            // logits / p (fp32); also split-K partials
__device__ float    g_cn[N1];                        // center norms
__device__ float    g_Hn[(size_t)N1 * D];            // h_next fp32
__device__ unsigned g_hPhi[(size_t)N0 * (D / 2)];    // h pairs
__device__ unsigned g_hPlo[(size_t)N0 * (D / 2)];
__device__ unsigned g_cPhi[(size_t)N1 * (D / 2)];    // centers pairs
__device__ unsigned g_cPlo[(size_t)N1 * (D / 2)];
__device__ unsigned g_wPhi[(size_t)D * (D / 2)];     // W pairs
__device__ unsigned g_wPlo[(size_t)D * (D / 2)];
__device__ unsigned g_GThi[(size_t)N1 * (N0 / 2)];   // p^T pairs
__device__ unsigned g_GTlo[(size_t)N1 * (N0 / 2)];
__device__ unsigned g_tThi[(size_t)D * (N0 / 2)];    // t^T pairs
__device__ unsigned g_tTlo[(size_t)D * (N0 / 2)];

// ------------------------------- helpers -----------------------------------
__device__ __forceinline__ unsigned bf16_hi_bits(float v, float& rem) {
    __nv_bfloat16 h = __float2bfloat16_rn(v);
    rem = v - __bfloat162float(h);
    return (unsigned)*reinterpret_cast<unsigned short*>(&h);
}
__device__ __forceinline__ unsigned bf16_bits(float v) {
    __nv_bfloat16 h = __float2bfloat16_rn(v);
    return (unsigned)*reinterpret_cast<unsigned short*>(&h);
}
__device__ __forceinline__ float fast_tanh(float x) {
    x = fminf(10.f, fmaxf(-10.f, x));
    float u = __expf(2.f * x);
    return __fdividef(u - 1.f, u + 1.f);
}

// split-pack: X fp32 [n*2 elems] -> hi/lo pair arrays (u32 per 2 elems)
__global__ __launch_bounds__(256)
void split_pack(const float* __restrict__ X, unsigned* __restrict__ hi,
                unsigned* __restrict__ lo, size_t npairs)
{
    size_t i = (size_t)blockIdx.x * 256 + threadIdx.x;
    if (i >= npairs) return;
    float2 v = reinterpret_cast<const float2*>(X)[i];
    float ra, rb;
    unsigned ha = bf16_hi_bits(v.x, ra);
    unsigned hb = bf16_hi_bits(v.y, rb);
    hi[i] = ha | (hb << 16);
    lo[i] = bf16_bits(ra) | (bf16_bits(rb) << 16);
}

// transpose + split: G [R][C] fp32 -> GT hi/lo [C][R/2] pairs along R
__global__ __launch_bounds__(256)
void transpose_split(const float* __restrict__ G, unsigned* __restrict__ hi,
                     unsigned* __restrict__ lo, int R, int C)
{
    __shared__ float tile[32][33];
    const int r0 = blockIdx.x * 32, c0 = blockIdx.y * 32;
    const int tid = threadIdx.x;
    for (int i = tid; i < 1024; i += 256) {
        int rl = i >> 5, cl = i & 31;
        tile[cl][rl] = G[(size_t)(r0 + rl) * C + c0 + cl];
    }
    __syncthreads();
    for (int i = tid; i < 512; i += 256) {
        int cl = i >> 4, p = i & 15;
        float a = tile[cl][2 * p], b = tile[cl][2 * p + 1];
        float ra, rb;
        unsigned ha = bf16_hi_bits(a, ra);
        unsigned hb = bf16_hi_bits(b, rb);
        size_t o = (size_t)(c0 + cl) * (size_t)(R >> 1) + (r0 >> 1) + p;
        hi[o] = ha | (hb << 16);
        lo[o] = bf16_bits(ra) | (bf16_bits(rb) << 16);
    }
}

// row norms: cn[row] = sum_k C[row,k]^2  (d = 1024)
__global__ __launch_bounds__(256)
void row_norm(const float* __restrict__ C, float* __restrict__ cn, int d)
{
    __shared__ float red[256];
    const int row = blockIdx.x;
    const float* c = C + (size_t)row * d;
    float s = 0.f;
    for (int j = threadIdx.x; j < d; j += 256) { float v = c[j]; s = fmaf(v, v, s); }
    red[threadIdx.x] = s; __syncthreads();
    for (int st = 128; st > 0; st >>= 1) {
        if (threadIdx.x < st) red[threadIdx.x] += red[threadIdx.x + st];
        __syncthreads();
    }
    if (threadIdx.x == 0) cn[row] = red[0];
}

// row softmax of logits = 0.5*G - 0.25*cn, in place on G. cols <= 2048.
__global__ __launch_bounds__(256)
void softmax_rows(float* __restrict__ G, const float* __restrict__ cn, int cols)
{
    __shared__ float red[256];
    const int row = blockIdx.x;
    float* g = G + (size_t)row * cols;
    const int tid = threadIdx.x;

    float l[8];
    float m = -1e30f;
    int cnt = 0;
    for (int j = tid; j < cols; j += 256) {
        float v = 0.5f * g[j] - 0.25f * cn[j];
        l[cnt++] = v;
        m = fmaxf(m, v);
    }
    red[tid] = m; __syncthreads();
    for (int st = 128; st > 0; st >>= 1) {
        if (tid < st) red[tid] = fmaxf(red[tid], red[tid + st]);
        __syncthreads();
    }
    m = red[0];
    __syncthreads();

    float s = 0.f;
    for (int c = 0; c < cnt; c++) { float e = __expf(l[c] - m); l[c] = e; s += e; }
    red[tid] = s; __syncthreads();
    for (int st = 128; st > 0; st >>= 1) {
        if (tid < st) red[tid] += red[tid + st];
        __syncthreads();
    }
    float inv = 1.f / red[0];

    cnt = 0;
    for (int j = tid; j < cols; j += 256) g[j] = l[cnt++] * inv;
}

// c = a + b elementwise (float4 vectorized); n multiple of 4
__global__ __launch_bounds__(256)
void add2(const float* __restrict__ a, const float* __restrict__ b,
          float* __restrict__ c, size_t n4)
{
    size_t i = (size_t)blockIdx.x * 256 + threadIdx.x;
    if (i >= n4) return;
    float4 x = reinterpret_cast<const float4*>(a)[i];
    float4 y = reinterpret_cast<const float4*>(b)[i];
    x.x += y.x; x.y += y.y; x.z += y.z; x.w += y.w;
    reinterpret_cast<float4*>(c)[i] = x;
}

// ---------------------------------------------------------------------------
// split-3 bf16 tensor GEMM: C[M,N] = A[M,K'] * B[N,K']^T over K elems starting
// at elem offset 2*koff (koff in u32 pairs). ldA/ldB = row strides in u32.
// 128 threads, 4 warps of 64x64. fp32 accumulate.
// EPI 0: fp32 store to C (row/col guarded).
// EPI 1: v = fast_tanh(acc + bias[col]); write v transposed+split to Thi/Tlo
//        [N rows][M/2 pair cols]  (requires M%128==0, N%128==0).
// ---------------------------------------------------------------------------
#define BK 32
#define KPT 16        // u32 pairs per tile row per iter
#define TSTR 20       // padded smem row stride (u32); 80B rows, 16B-aligned
#define TILE_U32 (128 * TSTR)
#define SMEM_BYTES (2 * 4 * TILE_U32 * 4)

__device__ __forceinline__ void mma_bf16(float* c, const unsigned* a, const unsigned* b)
{
    asm volatile(
        "mma.sync.aligned.m16n8k16.row.col.f32.bf16.bf16.f32 "
        "{%0,%1,%2,%3}, {%4,%5,%6,%7}, {%8,%9}, {%0,%1,%2,%3};"
        : "+f"(c[0]), "+f"(c[1]), "+f"(c[2]), "+f"(c[3])
        : "r"(a[0]), "r"(a[1]), "r"(a[2]), "r"(a[3]), "r"(b[0]), "r"(b[1]));
}

__device__ __forceinline__ void ldmx4(unsigned* r, unsigned a)
{
    asm volatile("ldmatrix.sync.aligned.m8n8.x4.shared.b16 {%0,%1,%2,%3}, [%4];"
                 : "=r"(r[0]), "=r"(r[1]), "=r"(r[2]), "=r"(r[3]) : "r"(a));
}

__device__ __forceinline__ void cpa16(unsigned dst, const void* src, bool pred)
{
    int sz = pred ? 16 : 0;
    asm volatile("cp.async.ca.shared.global [%0], [%1], 16, %2;\n"
                 :: "r"(dst), "l"(src), "r"(sz));
}

template <int EPI>
__global__ __launch_bounds__(128)
void gemm4(const unsigned* __restrict__ Ahi, const unsigned* __restrict__ Alo,
           const unsigned* __restrict__ Bhi, const unsigned* __restrict__ Blo,
           const float* __restrict__ bias, float* __restrict__ C,
           unsigned* __restrict__ Thi, unsigned* __restrict__ Tlo,
           int M, int N, int K, int ldA, int ldB, int koff)
{
    extern __shared__ __align__(16) unsigned dynbuf[];
    const int tid  = threadIdx.x;
    const int bm   = blockIdx.y * 128, bn = blockIdx.x * 128;
    const int lane = tid & 31, wid = tid >> 5;
    const int wr   = (wid >> 1) * 64, wc = (wid & 1) * 64;
    const int g    = lane >> 2, t = lane & 3;

    float acc[4][8][4];
#pragma unroll
    for (int mi = 0; mi < 4; mi++)
#pragma unroll
        for (int ni = 0; ni < 8; ni++)
#pragma unroll
            for (int k = 0; k < 4; k++) acc[mi][ni][k] = 0.f;

    const int NIT = K / BK;
    const unsigned sbase = (unsigned)__cvta_generic_to_shared(dynbuf);
    const unsigned matoff = (((unsigned)(lane & 15) * TSTR) + (((unsigned)lane >> 4) << 2)) * 4;

    auto prefetch = [&](int it, int s) {
        const int kp0 = koff + it * KPT;
        const unsigned stg = sbase + (unsigned)s * (4 * TILE_U32 * 4);
#pragma unroll
        for (int h = 0; h < 4; h++) {
            int c = tid + h * 128;           // 0..511
            int row = c >> 2, seg = (c & 3) << 2;
            unsigned soff = (unsigned)(row * TSTR + seg) * 4;
            bool pa = (bm + row) < M;
            bool pb = (bn + row) < N;
            size_t ga = (size_t)(pa ? bm + row : 0) * ldA + kp0 + seg;
            size_t gb = (size_t)(pb ? bn + row : 0) * ldB + kp0 + seg;
            cpa16(stg + 0 * TILE_U32 * 4 + soff, Ahi + ga, pa);
            cpa16(stg + 1 * TILE_U32 * 4 + soff, Alo + ga, pa);
            cpa16(stg + 2 * TILE_U32 * 4 + soff, Bhi + gb, pb);
            cpa16(stg + 3 * TILE_U32 * 4 + soff, Blo + gb, pb);
        }
    };

    prefetch(0, 0);
    asm volatile("cp.async.commit_group;\n");

    for (int it = 0; it < NIT; ++it) {
        const int s = it & 1;
        if (it + 1 < NIT) {
            prefetch(it + 1, s ^ 1);
            asm volatile("cp.async.commit_group;\n");
            asm volatile("cp.async.wait_group 1;\n");
        } else {
            asm volatile("cp.async.wait_group 0;\n");
        }
        __syncthreads();

        const unsigned sA_hi = sbase + (unsigned)(s * 4 + 0) * (TILE_U32 * 4);
        const unsigned sA_lo = sbase + (unsigned)(s * 4 + 1) * (TILE_U32 * 4);
        const unsigned sB_hi = sbase + (unsigned)(s * 4 + 2) * (TILE_U32 * 4);
        const unsigned sB_lo = sbase + (unsigned)(s * 4 + 3) * (TILE_U32 * 4);

#pragma unroll
        for (int ks = 0; ks < 2; ks++) {
            unsigned ah[4][4], al[4][4], bh[8][2], bl[8][2];
#pragma unroll
            for (int mi = 0; mi < 4; mi++) {
                unsigned off = matoff + (unsigned)((wr + mi * 16) * TSTR + ks * 8) * 4;
                ldmx4(ah[mi], sA_hi + off);
                ldmx4(al[mi], sA_lo + off);
            }
#pragma unroll
            for (int nj = 0; nj < 4; nj++) {
                unsigned off = matoff + (unsigned)((wc + nj * 16) * TSTR + ks * 8) * 4;
                unsigned bt[4];
                ldmx4(bt, sB_hi + off);
                bh[2 * nj][0] = bt[0]; bh[2 * nj + 1][0] = bt[1];
                bh[2 * nj][1] = bt[2]; bh[2 * nj + 1][1] = bt[3];
                ldmx4(bt, sB_lo + off);
                bl[2 * nj][0] = bt[0]; bl[2 * nj + 1][0] = bt[1];
                bl[2 * nj][1] = bt[2]; bl[2 * nj + 1][1] = bt[3];
            }
#pragma unroll
            for (int mi = 0; mi < 4; mi++)
#pragma unroll
                for (int ni = 0; ni < 8; ni++) {
                    mma_bf16(acc[mi][ni], ah[mi], bh[ni]);
                    mma_bf16(acc[mi][ni], ah[mi], bl[ni]);
                    mma_bf16(acc[mi][ni], al[mi], bh[ni]);
                }
        }
        __syncthreads();
    }

    if (EPI == 0) {
#pragma unroll
        for (int mi = 0; mi < 4; mi++) {
            int r = bm + wr + mi * 16 + g;
#pragma unroll
            for (int ni = 0; ni < 8; ni++) {
                int cc = bn + wc + ni * 8 + 2 * t;
                if (cc < N) {
                    if (r < M)
                        *reinterpret_cast<float2*>(&C[(size_t)r * N + cc]) =
                            make_float2(acc[mi][ni][0], acc[mi][ni][1]);
                    if (r + 8 < M)
                        *reinterpret_cast<float2*>(&C[(size_t)(r + 8) * N + cc]) =
                            make_float2(acc[mi][ni][2], acc[mi][ni][3]);
                }
            }
        }
    } else {
        // tanh + write transposed split pairs: T[n][m/2]
        const size_t Mh = (size_t)(M >> 1);
#pragma unroll
        for (int mi = 0; mi < 4; mi++) {
            int mglob = bm + wr + mi * 16 + g;        // row of v0/v1; +8 for v2/v3
#pragma unroll
            for (int ni = 0; ni < 8; ni++) {
                int cc = bn + wc + ni * 8 + 2 * t;
                float b0 = bias[cc], b1 = bias[cc + 1];
                float v[4];
                v[0] = fast_tanh(acc[mi][ni][0] + b0);
                v[1] = fast_tanh(acc[mi][ni][1] + b1);
                v[2] = fast_tanh(acc[mi][ni][2] + b0);
                v[3] = fast_tanh(acc[mi][ni][3] + b1);
#pragma unroll
                for (int vi = 0; vi < 4; vi++) {
                    float rem;
                    unsigned hb = bf16_hi_bits(v[vi], rem);
                    unsigned lb = bf16_bits(rem);
                    unsigned pkt = hb | (lb << 16);
                    unsigned oth = __shfl_xor_sync(0xffffffffu, pkt, 4);
                    if ((lane & 4) == 0) {
                        unsigned hi_u = (pkt & 0xffffu) | ((oth & 0xffffu) << 16);
                        unsigned lo_u = (pkt >> 16) | (oth & 0xffff0000u);
                        int n = cc + (vi & 1);
                        int mp = ((mglob + ((vi >> 1) << 3)) >> 1);
                        size_t off = (size_t)n * Mh + mp;
                        Thi[off] = hi_u;
                        Tlo[off] = lo_u;
                    }
                }
            }
        }
    }
}

// ---------------------------------------------------------------------------
// Host orchestration
// ---------------------------------------------------------------------------
static void run_level(const float* h_fp32, unsigned* hPhi, unsigned* hPlo,
                      const float* centers, const float* W, const float* b,
                      int n_prev, int n_cur,
                      unsigned* cPhi, unsigned* cPlo,
                      unsigned* wPhi, unsigned* wPlo,
                      float* G, float* cn,
                      unsigned* GThi, unsigned* GTlo,
                      unsigned* tThi, unsigned* tTlo,
                      float* out)
{
    const int ldD = D / 2;
    // pack inputs
    {
        size_t np = (size_t)n_prev * (D / 2);
        split_pack<<<(unsigned)((np + 255) / 256), 256>>>(h_fp32, hPhi, hPlo, np);
        np = (size_t)n_cur * (D / 2);
        split_pack<<<(unsigned)((np + 255) / 256), 256>>>(centers, cPhi, cPlo, np);
        np = (size_t)D * (D / 2);
        split_pack<<<(unsigned)((np + 255) / 256), 256>>>(W, wPhi, wPlo, np);
    }
    row_norm<<<n_cur, 256>>>(centers, cn, D);

    // G = h @ c^T
    {
        dim3 grid((n_cur + 127) / 128, (n_prev + 127) / 128);
        gemm4<0><<<grid, 128, SMEM_BYTES>>>(hPhi, hPlo, cPhi, cPlo, nullptr, G,
                                            nullptr, nullptr, n_prev, n_cur, D,
                                            ldD, ldD, 0);
    }
    softmax_rows<<<n_prev, 256>>>(G, cn, n_cur);
    transpose_split<<<dim3(n_prev / 32, (n_cur + 31) / 32), 256>>>(G, GThi, GTlo,
                                                                   n_prev, n_cur);
    // t = tanh(h @ W^T + b), written transposed+split
    {
        dim3 grid(D / 128, n_prev / 128);
        gemm4<1><<<grid, 128, SMEM_BYTES>>>(hPhi, hPlo, wPhi, wPlo, b, nullptr,
                                            tThi, tTlo, n_prev, D, D, ldD, ldD, 0);
    }
    // out = p^T @ t  (NT on the transposed pair arrays), K = n_prev
    {
        const int ldK = n_prev / 2;
        dim3 grid(D / 128, (n_cur + 127) / 128);
        if (n_prev >= 8192) {
            // split-K = 2; partials into g_G (free after transpose_split)
            float* P0 = G;
            float* P1 = G + (size_t)n_cur * D;
            int Kh = n_prev / 2;
            gemm4<0><<<grid, 128, SMEM_BYTES>>>(GThi, GTlo, tThi, tTlo, nullptr, P0,
                                                nullptr, nullptr, n_cur, D, Kh,
                                                ldK, ldK, 0);
            gemm4<0><<<grid, 128, SMEM_BYTES>>>(GThi, GTlo, tThi, tTlo, nullptr, P1,
                                                nullptr, nullptr, n_cur, D, Kh,
                                                ldK, ldK, Kh / 2);
            size_t n4 = (size_t)n_cur * D / 4;
            add2<<<(unsigned)((n4 + 255) / 256), 256>>>(P0, P1, out, n4);
        } else {
            gemm4<0><<<grid, 128, SMEM_BYTES>>>(GThi, GTlo, tThi, tTlo, nullptr, out,
                                                nullptr, nullptr, n_cur, D, n_prev,
                                                ldK, ldK, 0);
        }
    }
}

extern "C" void kernel_launch(void* const* d_in, const int* in_sizes, int n_in,
                              void* d_out, int out_size)
{
    const float* h0 = (const float*)d_in[0];
    const float* c1 = (const float*)d_in[1];
    const float* c2 = (const float*)d_in[2];
    const float* c3 = (const float*)d_in[3];
    const float* W1 = (const float*)d_in[4];
    const float* b1 = (const float*)d_in[5];
    const float* W2 = (const float*)d_in[6];
    const float* b2 = (const float*)d_in[7];
    const float* W3 = (const float*)d_in[8];
    const float* b3 = (const float*)d_in[9];
    float* out = (float*)d_out;

    cudaFuncSetAttribute(gemm4<0>, cudaFuncAttributeMaxDynamicSharedMemorySize, SMEM_BYTES);
    cudaFuncSetAttribute(gemm4<1>, cudaFuncAttributeMaxDynamicSharedMemorySize, SMEM_BYTES);

    float *pG, *pcn, *pHn;
    unsigned *hPhi, *hPlo, *cPhi, *cPlo, *wPhi, *wPlo, *GThi, *GTlo, *tThi, *tTlo;
    cudaGetSymbolAddress((void**)&pG,   g_G);
    cudaGetSymbolAddress((void**)&pcn,  g_cn);
    cudaGetSymbolAddress((void**)&pHn,  g_Hn);
    cudaGetSymbolAddress((void**)&hPhi, g_hPhi);
    cudaGetSymbolAddress((void**)&hPlo, g_hPlo);
    cudaGetSymbolAddress((void**)&cPhi, g_cPhi);
    cudaGetSymbolAddress((void**)&cPlo, g_cPlo);
    cudaGetSymbolAddress((void**)&wPhi, g_wPhi);
    cudaGetSymbolAddress((void**)&wPlo, g_wPlo);
    cudaGetSymbolAddress((void**)&GThi, g_GThi);
    cudaGetSymbolAddress((void**)&GTlo, g_GTlo);
    cudaGetSymbolAddress((void**)&tThi, g_tThi);
    cudaGetSymbolAddress((void**)&tTlo, g_tTlo);

    // Level 1: 16384 -> 2048
    run_level(h0, hPhi, hPlo, c1, W1, b1, N0, N1,
              cPhi, cPlo, wPhi, wPlo, pG, pcn, GThi, GTlo, tThi, tTlo, pHn);
    // Level 2: 2048 -> 256
    run_level(pHn, hPhi, hPlo, c2, W2, b2, N1, N2,
              cPhi, cPlo, wPhi, wPlo, pG, pcn, GThi, GTlo, tThi, tTlo, pHn);
    // Level 3: 256 -> 32 (final output fp32 to d_out)
    run_level(pHn, hPhi, hPlo, c3, W3, b3, N2, N3,
              cPhi, cPlo, wPhi, wPlo, pG, pcn, GThi, GTlo, tThi, tTlo, out);
}

// round 6
// speedup vs baseline: 1.3653x; 1.3653x over previous
#include <cuda_runtime.h>
#include <cuda_fp16.h>
#include <math.h>

// ---------------------------------------------------------------------------
// HierarchicalClustering via split-fp16 tensor-core GEMMs (mma.sync HMMA).
//   logits = 0.5*(h @ c^T) - 0.25*||c||^2   (||h||^2 cancels in softmax)
//   p      = softmax_rows(logits)
//   t      = tanh(h @ W^T + b)
//   h_next = p^T @ t
// Operand format: fp16 pair-packed u32 arrays [rows][K/2] (u32 = {f16 even-k,
// f16 odd-k}). Precision schemes (fp32 accumulate):
//   logits : (h_hi,h_lo) x (c_hi,c_lo), 3 MMAs (hh+hl+lh)   err ~2^-22
//   t      : (h_hi,h_lo) x (W_hi),      2 MMAs (hh+lh)      err ~2^-12 rel
//   out    : (p_hi,p_lo) x (t_hi),      2 MMAs (hh+lh)      err ~p*2^-12*t
// ---------------------------------------------------------------------------

#define D 1024
#define N0 16384
#define N1 2048
#define N2 256
#define N3 32

// ------------------------- scratch (device globals) ------------------------
__device__ float    g_G[(size_t)N0 * N1];            // logits; later split-K partials
__device__ float    g_cnq[N1];                       // 0.25*||c||^2
__device__ float    g_Hn[(size_t)N1 * D];            // h_next fp32
__device__ unsigned g_hPhi[(size_t)N0 * (D / 2)];    // h pairs
__device__ unsigned g_hPlo[(size_t)N0 * (D / 2)];
__device__ unsigned g_cPhi[(size_t)N1 * (D / 2)];    // centers pairs
__device__ unsigned g_cPlo[(size_t)N1 * (D / 2)];
__device__ unsigned g_wPhi[(size_t)D * (D / 2)];     // W hi pairs
__device__ unsigned g_GThi[(size_t)N1 * (N0 / 2)];   // p^T pairs
__device__ unsigned g_GTlo[(size_t)N1 * (N0 / 2)];
__device__ unsigned g_tT[(size_t)D * (N0 / 2)];      // t^T fp16 pairs (hi only)

// ------------------------------- helpers -----------------------------------
__device__ __forceinline__ unsigned h_bits(float v) {
    return (unsigned)__half_as_ushort(__float2half_rn(v));
}
__device__ __forceinline__ unsigned h_hi(float v, float& rem) {
    __half h = __float2half_rn(v);
    rem = v - __half2float(h);
    return (unsigned)__half_as_ushort(h);
}
__device__ __forceinline__ float fast_tanh(float x) {
    x = fminf(10.f, fmaxf(-10.f, x));
    float u = __expf(2.f * x);
    return __fdividef(u - 1.f, u + 1.f);
}

// pack hi+lo pairs
__global__ __launch_bounds__(256)
void pack_pair(const float* __restrict__ X, unsigned* __restrict__ hi,
               unsigned* __restrict__ lo, size_t npairs)
{
    size_t i = (size_t)blockIdx.x * 256 + threadIdx.x;
    if (i >= npairs) return;
    float2 v = reinterpret_cast<const float2*>(X)[i];
    float ra, rb;
    unsigned ha = h_hi(v.x, ra);
    unsigned hb = h_hi(v.y, rb);
    hi[i] = ha | (hb << 16);
    lo[i] = h_bits(ra) | (h_bits(rb) << 16);
}

// pack hi only (for W)
__global__ __launch_bounds__(256)
void pack_hi_only(const float* __restrict__ X, unsigned* __restrict__ hi, size_t npairs)
{
    size_t i = (size_t)blockIdx.x * 256 + threadIdx.x;
    if (i >= npairs) return;
    float2 v = reinterpret_cast<const float2*>(X)[i];
    hi[i] = h_bits(v.x) | (h_bits(v.y) << 16);
}

// pack centers (hi+lo) + cnq = 0.25*||c||^2. One block per row, row = 2*dpairs.
__global__ __launch_bounds__(256)
void pack_c(const float* __restrict__ X, unsigned* __restrict__ hi,
            unsigned* __restrict__ lo, float* __restrict__ cnq, int dpairs)
{
    __shared__ float red[256];
    const int row = blockIdx.x;
    const float2* src = reinterpret_cast<const float2*>(X) + (size_t)row * dpairs;
    float s = 0.f;
    for (int i = threadIdx.x; i < dpairs; i += 256) {
        float2 v = src[i];
        float ra, rb;
        unsigned ha = h_hi(v.x, ra);
        unsigned hb = h_hi(v.y, rb);
        size_t o = (size_t)row * dpairs + i;
        hi[o] = ha | (hb << 16);
        lo[o] = h_bits(ra) | (h_bits(rb) << 16);
        s = fmaf(v.x, v.x, s); s = fmaf(v.y, v.y, s);
    }
    red[threadIdx.x] = s; __syncthreads();
    for (int st = 128; st > 0; st >>= 1) {
        if (threadIdx.x < st) red[threadIdx.x] += red[threadIdx.x + st];
        __syncthreads();
    }
    if (threadIdx.x == 0) cnq[row] = 0.25f * red[0];
}

// ---------------------------------------------------------------------------
// Fused softmax + transpose + fp16 split pack.
// G [R][C] holds final logits. Per 32-row slab: compute row max & expsum, then
// write p^T as hi/lo pairs: GT[c][r/2].  R%32==0; C in {2048,256,32}.
// ---------------------------------------------------------------------------
__global__ __launch_bounds__(256)
void softmax_transpose(const float* __restrict__ G, unsigned* __restrict__ hi,
                       unsigned* __restrict__ lo, int R, int C)
{
    __shared__ float red[32][9];
    __shared__ float smx[32], sinv[32];
    __shared__ float tile[32][65];
    const int tid = threadIdx.x;
    const int r0 = blockIdx.x * 32;
    const int row = tid >> 3, l8 = tid & 7;
    const float* gr = G + (size_t)(r0 + row) * C;
    const int c4n = C >> 2;

    // pass 1: row max
    float m = -1e30f;
    for (int c4 = l8; c4 < c4n; c4 += 8) {
        float4 v = reinterpret_cast<const float4*>(gr)[c4];
        m = fmaxf(m, fmaxf(fmaxf(v.x, v.y), fmaxf(v.z, v.w)));
    }
    red[row][l8] = m;
    __syncthreads();
    if (tid < 32) {
        float mm = red[tid][0];
#pragma unroll
        for (int j = 1; j < 8; j++) mm = fmaxf(mm, red[tid][j]);
        smx[tid] = mm;
    }
    __syncthreads();
    m = smx[row];

    // pass 2: exp sum
    float s = 0.f;
    for (int c4 = l8; c4 < c4n; c4 += 8) {
        float4 v = reinterpret_cast<const float4*>(gr)[c4];
        s += __expf(v.x - m) + __expf(v.y - m) + __expf(v.z - m) + __expf(v.w - m);
    }
    __syncthreads();
    red[row][l8] = s;
    __syncthreads();
    if (tid < 32) {
        float ss = 0.f;
#pragma unroll
        for (int j = 0; j < 8; j++) ss += red[tid][j];
        sinv[tid] = 1.f / ss;
    }
    __syncthreads();

    // pass 3: transform + transpose + pack (64-col chunks, L2-hot reread)
    const size_t Rh = (size_t)(R >> 1);
    const float* gbase = G + (size_t)r0 * C;
    for (int c0 = 0; c0 < C; c0 += 64) {
        const int cw = (C - c0 >= 64) ? 64 : (C - c0);
        const int csh = (cw == 64) ? 6 : 5;   // cw is 64 or 32
        for (int i = tid; i < 32 * cw; i += 256) {
            int r = i >> csh, cl = i & (cw - 1);
            tile[r][cl] = gbase[(size_t)r * C + c0 + cl];
        }
        __syncthreads();
        for (int i = tid; i < cw * 16; i += 256) {
            int c = i >> 4, p = i & 15;
            float ea = __expf(tile[2 * p][c] - smx[2 * p]) * sinv[2 * p];
            float eb = __expf(tile[2 * p + 1][c] - smx[2 * p + 1]) * sinv[2 * p + 1];
            float ra, rb;
            unsigned ha = h_hi(ea, ra);
            unsigned hb = h_hi(eb, rb);
            size_t o = (size_t)(c0 + c) * Rh + (r0 >> 1) + p;
            hi[o] = ha | (hb << 16);
            lo[o] = h_bits(ra) | (h_bits(rb) << 16);
        }
        __syncthreads();
    }
}

// sum S split-K slices; write fp32 out and optionally h pairs
__global__ __launch_bounds__(256)
void addS_pack(const float* __restrict__ P, float* __restrict__ out,
               unsigned* __restrict__ hi, unsigned* __restrict__ lo,
               size_t n4, size_t str4, int S)
{
    size_t i = (size_t)blockIdx.x * 256 + threadIdx.x;
    if (i >= n4) return;
    const float4* p4 = reinterpret_cast<const float4*>(P);
    float4 a = p4[i];
    for (int s = 1; s < S; s++) {
        float4 b = p4[i + (size_t)s * str4];
        a.x += b.x; a.y += b.y; a.z += b.z; a.w += b.w;
    }
    reinterpret_cast<float4*>(out)[i] = a;
    if (hi) {
        float r0, r1, r2, r3;
        unsigned h0 = h_hi(a.x, r0), h1 = h_hi(a.y, r1);
        unsigned h2 = h_hi(a.z, r2), h3 = h_hi(a.w, r3);
        hi[2 * i]     = h0 | (h1 << 16);
        hi[2 * i + 1] = h2 | (h3 << 16);
        lo[2 * i]     = h_bits(r0) | (h_bits(r1) << 16);
        lo[2 * i + 1] = h_bits(r2) | (h_bits(r3) << 16);
    }
}

// ---------------------------------------------------------------------------
// split fp16 tensor GEMM: C[M,N] = A[M,K] * B[N,K]^T over K elems starting at
// pair offset koff (+ blockIdx.z * kqPairs for split-K; output slice offset
// blockIdx.z * sliceElems). ldA/ldB in u32 pairs.
// NMMA=3: Ahi,Alo,Bhi,Blo -> hh+hl+lh.   NMMA=2: Ahi,Alo,Bhi -> hh+lh.
// EPI 0: plain fp32 store. EPI 1: tanh(acc+aux[col]) -> transposed fp16 pairs
// into Tt [N][M/2]. EPI 2: store 0.5*acc - aux[col].
// ---------------------------------------------------------------------------
#define BK 32
#define KPT 16
#define TSTR 20
#define TILE_U32 (128 * TSTR)
#define SMEM3 (2 * 4 * TILE_U32 * 4)
#define SMEM2 (2 * 3 * TILE_U32 * 4)

__device__ __forceinline__ void mma_f16(float* c, const unsigned* a, const unsigned* b)
{
    asm volatile(
        "mma.sync.aligned.m16n8k16.row.col.f32.f16.f16.f32 "
        "{%0,%1,%2,%3}, {%4,%5,%6,%7}, {%8,%9}, {%0,%1,%2,%3};"
        : "+f"(c[0]), "+f"(c[1]), "+f"(c[2]), "+f"(c[3])
        : "r"(a[0]), "r"(a[1]), "r"(a[2]), "r"(a[3]), "r"(b[0]), "r"(b[1]));
}
__device__ __forceinline__ void ldmx4(unsigned* r, unsigned a)
{
    asm volatile("ldmatrix.sync.aligned.m8n8.x4.shared.b16 {%0,%1,%2,%3}, [%4];"
                 : "=r"(r[0]), "=r"(r[1]), "=r"(r[2]), "=r"(r[3]) : "r"(a));
}
__device__ __forceinline__ void cpa16(unsigned dst, const void* src, bool pred)
{
    int sz = pred ? 16 : 0;
    asm volatile("cp.async.ca.shared.global [%0], [%1], 16, %2;\n"
                 :: "r"(dst), "l"(src), "r"(sz));
}

template <int NMMA, int EPI>
__global__ __launch_bounds__(256)
void gemm5(const unsigned* __restrict__ Ahi, const unsigned* __restrict__ Alo,
           const unsigned* __restrict__ Bhi, const unsigned* __restrict__ Blo,
           const float* __restrict__ aux, float* __restrict__ C,
           unsigned* __restrict__ Tt,
           int M, int N, int K, int ldA, int ldB, int koff,
           int kqPairs, size_t sliceElems)
{
    extern __shared__ __align__(16) unsigned dynbuf[];
    const int NBUF = (NMMA == 3) ? 4 : 3;
    const int tid  = threadIdx.x;
    const int bm   = blockIdx.y * 128, bn = blockIdx.x * 128;
    const int lane = tid & 31, wid = tid >> 5;
    const int wr   = (wid >> 2) * 64, wc = (wid & 3) * 32;
    const int g    = lane >> 2, t = lane & 3;
    const int kp0base = koff + blockIdx.z * kqPairs;
    float* Cz = C + (size_t)blockIdx.z * sliceElems;

    float acc[4][4][4];
#pragma unroll
    for (int mi = 0; mi < 4; mi++)
#pragma unroll
        for (int ni = 0; ni < 4; ni++)
#pragma unroll
            for (int k = 0; k < 4; k++) acc[mi][ni][k] = 0.f;

    const int NIT = K / BK;
    const unsigned sbase = (unsigned)__cvta_generic_to_shared(dynbuf);
    const unsigned matoff = (((unsigned)(lane & 15) * TSTR) + (((unsigned)lane >> 4) << 2)) * 4;

    auto prefetch = [&](int it, int s) {
        const int kp0 = kp0base + it * KPT;
        const unsigned stg = sbase + (unsigned)(s * NBUF) * (TILE_U32 * 4);
#pragma unroll
        for (int h = 0; h < 2; h++) {
            int c = tid + h * 256;
            int row = c >> 2, seg = (c & 3) << 2;
            unsigned soff = (unsigned)(row * TSTR + seg) * 4;
            bool pa = (bm + row) < M;
            bool pb = (bn + row) < N;
            size_t ga = (size_t)(pa ? bm + row : 0) * ldA + kp0 + seg;
            size_t gb = (size_t)(pb ? bn + row : 0) * ldB + kp0 + seg;
            cpa16(stg + 0 * TILE_U32 * 4 + soff, Ahi + ga, pa);
            cpa16(stg + 1 * TILE_U32 * 4 + soff, Alo + ga, pa);
            cpa16(stg + 2 * TILE_U32 * 4 + soff, Bhi + gb, pb);
            if (NMMA == 3)
                cpa16(stg + 3 * TILE_U32 * 4 + soff, Blo + gb, pb);
        }
    };

    prefetch(0, 0);
    asm volatile("cp.async.commit_group;\n");

    for (int it = 0; it < NIT; ++it) {
        const int s = it & 1;
        if (it + 1 < NIT) {
            prefetch(it + 1, s ^ 1);
            asm volatile("cp.async.commit_group;\n");
            asm volatile("cp.async.wait_group 1;\n");
        } else {
            asm volatile("cp.async.wait_group 0;\n");
        }
        __syncthreads();

        const unsigned sA_hi = sbase + (unsigned)(s * NBUF + 0) * (TILE_U32 * 4);
        const unsigned sA_lo = sbase + (unsigned)(s * NBUF + 1) * (TILE_U32 * 4);
        const unsigned sB_hi = sbase + (unsigned)(s * NBUF + 2) * (TILE_U32 * 4);
        const unsigned sB_lo = sbase + (unsigned)(s * NBUF + 3) * (TILE_U32 * 4);

#pragma unroll
        for (int ks = 0; ks < 2; ks++) {
            unsigned ah[4][4], al[4][4], bh[4][2], bl[4][2];
#pragma unroll
            for (int mi = 0; mi < 4; mi++) {
                unsigned off = matoff + (unsigned)((wr + mi * 16) * TSTR + ks * 8) * 4;
                ldmx4(ah[mi], sA_hi + off);
                ldmx4(al[mi], sA_lo + off);
            }
#pragma unroll
            for (int nj = 0; nj < 2; nj++) {
                unsigned off = matoff + (unsigned)((wc + nj * 16) * TSTR + ks * 8) * 4;
                unsigned bt[4];
                ldmx4(bt, sB_hi + off);
                bh[2 * nj][0] = bt[0]; bh[2 * nj + 1][0] = bt[1];
                bh[2 * nj][1] = bt[2]; bh[2 * nj + 1][1] = bt[3];
                if (NMMA == 3) {
                    ldmx4(bt, sB_lo + off);
                    bl[2 * nj][0] = bt[0]; bl[2 * nj + 1][0] = bt[1];
                    bl[2 * nj][1] = bt[2]; bl[2 * nj + 1][1] = bt[3];
                }
            }
#pragma unroll
            for (int mi = 0; mi < 4; mi++)
#pragma unroll
                for (int ni = 0; ni < 4; ni++) {
                    mma_f16(acc[mi][ni], ah[mi], bh[ni]);
                    if (NMMA == 3) mma_f16(acc[mi][ni], ah[mi], bl[ni]);
                    mma_f16(acc[mi][ni], al[mi], bh[ni]);
                }
        }
        __syncthreads();
    }

    if (EPI == 0 || EPI == 2) {
#pragma unroll
        for (int mi = 0; mi < 4; mi++) {
            int r = bm + wr + mi * 16 + g;
#pragma unroll
            for (int ni = 0; ni < 4; ni++) {
                int cc = bn + wc + ni * 8 + 2 * t;
                if (cc < N) {
                    float2 v0, v1;
                    if (EPI == 2) {
                        float a0 = aux[cc], a1 = aux[cc + 1];
                        v0 = make_float2(0.5f * acc[mi][ni][0] - a0,
                                         0.5f * acc[mi][ni][1] - a1);
                        v1 = make_float2(0.5f * acc[mi][ni][2] - a0,
                                         0.5f * acc[mi][ni][3] - a1);
                    } else {
                        v0 = make_float2(acc[mi][ni][0], acc[mi][ni][1]);
                        v1 = make_float2(acc[mi][ni][2], acc[mi][ni][3]);
                    }
                    if (r < M)
                        *reinterpret_cast<float2*>(&Cz[(size_t)r * N + cc]) = v0;
                    if (r + 8 < M)
                        *reinterpret_cast<float2*>(&Cz[(size_t)(r + 8) * N + cc]) = v1;
                }
            }
        }
    } else {
        // tanh + transposed single-fp16 pair store: Tt[n][m/2]
        const size_t Mh = (size_t)(M >> 1);
#pragma unroll
        for (int mi = 0; mi < 4; mi++) {
            int mglob = bm + wr + mi * 16 + g;
#pragma unroll
            for (int ni = 0; ni < 4; ni++) {
                int cc = bn + wc + ni * 8 + 2 * t;
                float b0 = aux[cc], b1 = aux[cc + 1];
                float v[4];
                v[0] = fast_tanh(acc[mi][ni][0] + b0);
                v[1] = fast_tanh(acc[mi][ni][1] + b1);
                v[2] = fast_tanh(acc[mi][ni][2] + b0);
                v[3] = fast_tanh(acc[mi][ni][3] + b1);
#pragma unroll
                for (int vi = 0; vi < 4; vi++) {
                    unsigned hb = h_bits(v[vi]);
                    unsigned oth = __shfl_xor_sync(0xffffffffu, hb, 4);
                    if ((lane & 4) == 0) {
                        int n = cc + (vi & 1);
                        int mp = ((mglob + ((vi >> 1) << 3)) >> 1);
                        Tt[(size_t)n * Mh + mp] = hb | (oth << 16);
                    }
                }
            }
        }
    }
}

// ---------------------------------------------------------------------------
// Host orchestration
// ---------------------------------------------------------------------------
static void run_level(const float* h_fp32, bool need_pack_h,
                      unsigned* hPhi, unsigned* hPlo,
                      const float* centers, const float* W, const float* b,
                      int n_prev, int n_cur,
                      unsigned* cPhi, unsigned* cPlo, unsigned* wPhi,
                      float* G, float* cnq,
                      unsigned* GThi, unsigned* GTlo, unsigned* tT,
                      float* out, unsigned* outPhi, unsigned* outPlo)
{
    const int ldD = D / 2;
    if (need_pack_h) {
        size_t np = (size_t)n_prev * (D / 2);
        pack_pair<<<(unsigned)((np + 255) / 256), 256>>>(h_fp32, hPhi, hPlo, np);
    }
    pack_c<<<n_cur, 256>>>(centers, cPhi, cPlo, cnq, D / 2);
    {
        size_t np = (size_t)D * (D / 2);
        pack_hi_only<<<(unsigned)((np + 255) / 256), 256>>>(W, wPhi, np);
    }
    // logits = 0.5*h@c^T - cnq  (3-term)
    {
        dim3 grid((n_cur + 127) / 128, (n_prev + 127) / 128, 1);
        gemm5<3, 2><<<grid, 256, SMEM3>>>(hPhi, hPlo, cPhi, cPlo, cnq, G, nullptr,
                                          n_prev, n_cur, D, ldD, ldD, 0, 0, 0);
    }
    // p^T packed (fused softmax+transpose)
    softmax_transpose<<<n_prev / 32, 256>>>(G, GThi, GTlo, n_prev, n_cur);
    // t = tanh(h@W^T + b) -> transposed fp16 pairs (2-term)
    {
        dim3 grid(D / 128, n_prev / 128, 1);
        gemm5<2, 1><<<grid, 256, SMEM2>>>(hPhi, hPlo, wPhi, nullptr, b, nullptr, tT,
                                          n_prev, D, D, ldD, ldD, 0, 0, 0);
    }
    // out = p^T @ t  (2-term), split-K=4 via gridDim.z, partials in G
    {
        const int S = 4;
        const int ldK = n_prev / 2;
        const int Ks = n_prev / S;          // elems per slice
        dim3 grid(D / 128, (n_cur + 127) / 128, S);
        gemm5<2, 0><<<grid, 256, SMEM2>>>(GThi, GTlo, tT, nullptr, nullptr, G, nullptr,
                                          n_cur, D, Ks, ldK, ldK, 0,
                                          Ks / 2, (size_t)n_cur * D);
        size_t n4 = (size_t)n_cur * D / 4;
        addS_pack<<<(unsigned)((n4 + 255) / 256), 256>>>(G, out, outPhi, outPlo,
                                                         n4, n4, S);
    }
}

extern "C" void kernel_launch(void* const* d_in, const int* in_sizes, int n_in,
                              void* d_out, int out_size)
{
    const float* h0 = (const float*)d_in[0];
    const float* c1 = (const float*)d_in[1];
    const float* c2 = (const float*)d_in[2];
    const float* c3 = (const float*)d_in[3];
    const float* W1 = (const float*)d_in[4];
    const float* b1 = (const float*)d_in[5];
    const float* W2 = (const float*)d_in[6];
    const float* b2 = (const float*)d_in[7];
    const float* W3 = (const float*)d_in[8];
    const float* b3 = (const float*)d_in[9];
    float* out = (float*)d_out;

    cudaFuncSetAttribute(gemm5<3, 2>, cudaFuncAttributeMaxDynamicSharedMemorySize, SMEM3);
    cudaFuncSetAttribute(gemm5<2, 1>, cudaFuncAttributeMaxDynamicSharedMemorySize, SMEM2);
    cudaFuncSetAttribute(gemm5<2, 0>, cudaFuncAttributeMaxDynamicSharedMemorySize, SMEM2);

    float *pG, *pcnq, *pHn;
    unsigned *hPhi, *hPlo, *cPhi, *cPlo, *wPhi, *GThi, *GTlo, *tT;
    cudaGetSymbolAddress((void**)&pG,   g_G);
    cudaGetSymbolAddress((void**)&pcnq, g_cnq);
    cudaGetSymbolAddress((void**)&pHn,  g_Hn);
    cudaGetSymbolAddress((void**)&hPhi, g_hPhi);
    cudaGetSymbolAddress((void**)&hPlo, g_hPlo);
    cudaGetSymbolAddress((void**)&cPhi, g_cPhi);
    cudaGetSymbolAddress((void**)&cPlo, g_cPlo);
    cudaGetSymbolAddress((void**)&wPhi, g_wPhi);
    cudaGetSymbolAddress((void**)&GThi, g_GThi);
    cudaGetSymbolAddress((void**)&GTlo, g_GTlo);
    cudaGetSymbolAddress((void**)&tT,   g_tT);

    // Level 1: 16384 -> 2048 (h_next pairs written by addS_pack)
    run_level(h0, true, hPhi, hPlo, c1, W1, b1, N0, N1,
              cPhi, cPlo, wPhi, pG, pcnq, GThi, GTlo, tT, pHn, hPhi, hPlo);
    // Level 2: 2048 -> 256
    run_level(pHn, false, hPhi, hPlo, c2, W2, b2, N1, N2,
              cPhi, cPlo, wPhi, pG, pcnq, GThi, GTlo, tT, pHn, hPhi, hPlo);
    // Level 3: 256 -> 32 (final fp32 out; no pair pack needed)
    run_level(pHn, false, hPhi, hPlo, c3, W3, b3, N2, N3,
              cPhi, cPlo, wPhi, pG, pcnq, GThi, GTlo, tT, out, nullptr, nullptr);
}

// round 7
// speedup vs baseline: 1.5339x; 1.1235x over previous
#include <cuda_runtime.h>
#include <cuda_fp16.h>
#include <math.h>

// ---------------------------------------------------------------------------
// HierarchicalClustering via split-fp16 tensor-core GEMMs (mma.sync HMMA).
//   logits = 0.5*(h @ c^T) - 0.25*||c||^2   (||h||^2 cancels in softmax)
//   p      = softmax_rows(logits)
//   t      = tanh(h @ W^T + b)
//   h_next = p^T @ t
// Operand format: fp16 pair-packed u32 arrays [rows][K/2].
//   logits : (h_hi,h_lo) x (c_hi,c_lo), 3 MMAs    t: (h_hi,h_lo) x W_hi, 2 MMAs
//   out    : (p_hi,p_lo) x t_hi, 2 MMAs
// GEMM mainloop: 3-stage cp.async.cg pipeline, XOR-swizzled 64B smem rows,
// one __syncthreads per k-iteration, 2 CTAs/SM.
// ---------------------------------------------------------------------------

#define D 1024
#define N0 16384
#define N1 2048
#define N2 256
#define N3 32

// ------------------------- scratch (device globals) ------------------------
__device__ float    g_G[(size_t)N0 * N1];
__device__ float    g_cnq[N1];
__device__ float    g_Hn[(size_t)N1 * D];
__device__ unsigned g_hPhi[(size_t)N0 * (D / 2)];
__device__ unsigned g_hPlo[(size_t)N0 * (D / 2)];
__device__ unsigned g_cPhi[(size_t)N1 * (D / 2)];
__device__ unsigned g_cPlo[(size_t)N1 * (D / 2)];
__device__ unsigned g_wPhi[(size_t)D * (D / 2)];
__device__ unsigned g_GThi[(size_t)N1 * (N0 / 2)];
__device__ unsigned g_GTlo[(size_t)N1 * (N0 / 2)];
__device__ unsigned g_tT[(size_t)D * (N0 / 2)];

// ------------------------------- helpers -----------------------------------
__device__ __forceinline__ unsigned h_bits(float v) {
    return (unsigned)__half_as_ushort(__float2half_rn(v));
}
__device__ __forceinline__ unsigned h_hi(float v, float& rem) {
    __half h = __float2half_rn(v);
    rem = v - __half2float(h);
    return (unsigned)__half_as_ushort(h);
}
__device__ __forceinline__ float fast_tanh(float x) {
    x = fminf(10.f, fmaxf(-10.f, x));
    float u = __expf(2.f * x);
    return __fdividef(u - 1.f, u + 1.f);
}

__global__ __launch_bounds__(256)
void pack_pair(const float* __restrict__ X, unsigned* __restrict__ hi,
               unsigned* __restrict__ lo, size_t npairs)
{
    size_t i = (size_t)blockIdx.x * 256 + threadIdx.x;
    if (i >= npairs) return;
    float2 v = reinterpret_cast<const float2*>(X)[i];
    float ra, rb;
    unsigned ha = h_hi(v.x, ra);
    unsigned hb = h_hi(v.y, rb);
    hi[i] = ha | (hb << 16);
    lo[i] = h_bits(ra) | (h_bits(rb) << 16);
}

__global__ __launch_bounds__(256)
void pack_hi_only(const float* __restrict__ X, unsigned* __restrict__ hi, size_t npairs)
{
    size_t i = (size_t)blockIdx.x * 256 + threadIdx.x;
    if (i >= npairs) return;
    float2 v = reinterpret_cast<const float2*>(X)[i];
    hi[i] = h_bits(v.x) | (h_bits(v.y) << 16);
}

__global__ __launch_bounds__(256)
void pack_c(const float* __restrict__ X, unsigned* __restrict__ hi,
            unsigned* __restrict__ lo, float* __restrict__ cnq, int dpairs)
{
    __shared__ float red[256];
    const int row = blockIdx.x;
    const float2* src = reinterpret_cast<const float2*>(X) + (size_t)row * dpairs;
    float s = 0.f;
    for (int i = threadIdx.x; i < dpairs; i += 256) {
        float2 v = src[i];
        float ra, rb;
        unsigned ha = h_hi(v.x, ra);
        unsigned hb = h_hi(v.y, rb);
        size_t o = (size_t)row * dpairs + i;
        hi[o] = ha | (hb << 16);
        lo[o] = h_bits(ra) | (h_bits(rb) << 16);
        s = fmaf(v.x, v.x, s); s = fmaf(v.y, v.y, s);
    }
    red[threadIdx.x] = s; __syncthreads();
    for (int st = 128; st > 0; st >>= 1) {
        if (threadIdx.x < st) red[threadIdx.x] += red[threadIdx.x + st];
        __syncthreads();
    }
    if (threadIdx.x == 0) cnq[row] = 0.25f * red[0];
}

// Fused softmax + transpose + fp16 split pack. G [R][C]; GT[c][r/2] pairs.
__global__ __launch_bounds__(256)
void softmax_transpose(const float* __restrict__ G, unsigned* __restrict__ hi,
                       unsigned* __restrict__ lo, int R, int C)
{
    __shared__ float red[32][9];
    __shared__ float smx[32], sinv[32];
    __shared__ float tile[32][65];
    const int tid = threadIdx.x;
    const int r0 = blockIdx.x * 32;
    const int row = tid >> 3, l8 = tid & 7;
    const float* gr = G + (size_t)(r0 + row) * C;
    const int c4n = C >> 2;

    float m = -1e30f;
    for (int c4 = l8; c4 < c4n; c4 += 8) {
        float4 v = reinterpret_cast<const float4*>(gr)[c4];
        m = fmaxf(m, fmaxf(fmaxf(v.x, v.y), fmaxf(v.z, v.w)));
    }
    red[row][l8] = m;
    __syncthreads();
    if (tid < 32) {
        float mm = red[tid][0];
#pragma unroll
        for (int j = 1; j < 8; j++) mm = fmaxf(mm, red[tid][j]);
        smx[tid] = mm;
    }
    __syncthreads();
    m = smx[row];

    float s = 0.f;
    for (int c4 = l8; c4 < c4n; c4 += 8) {
        float4 v = reinterpret_cast<const float4*>(gr)[c4];
        s += __expf(v.x - m) + __expf(v.y - m) + __expf(v.z - m) + __expf(v.w - m);
    }
    __syncthreads();
    red[row][l8] = s;
    __syncthreads();
    if (tid < 32) {
        float ss = 0.f;
#pragma unroll
        for (int j = 0; j < 8; j++) ss += red[tid][j];
        sinv[tid] = 1.f / ss;
    }
    __syncthreads();

    const size_t Rh = (size_t)(R >> 1);
    const float* gbase = G + (size_t)r0 * C;
    for (int c0 = 0; c0 < C; c0 += 64) {
        const int cw = (C - c0 >= 64) ? 64 : (C - c0);
        const int csh = (cw == 64) ? 6 : 5;
        for (int i = tid; i < 32 * cw; i += 256) {
            int r = i >> csh, cl = i & (cw - 1);
            tile[r][cl] = gbase[(size_t)r * C + c0 + cl];
        }
        __syncthreads();
        for (int i = tid; i < cw * 16; i += 256) {
            int c = i >> 4, p = i & 15;
            float ea = __expf(tile[2 * p][c] - smx[2 * p]) * sinv[2 * p];
            float eb = __expf(tile[2 * p + 1][c] - smx[2 * p + 1]) * sinv[2 * p + 1];
            float ra, rb;
            unsigned ha = h_hi(ea, ra);
            unsigned hb = h_hi(eb, rb);
            size_t o = (size_t)(c0 + c) * Rh + (r0 >> 1) + p;
            hi[o] = ha | (hb << 16);
            lo[o] = h_bits(ra) | (h_bits(rb) << 16);
        }
        __syncthreads();
    }
}

// sum S split-K slices; write fp32 out and optionally h pairs
__global__ __launch_bounds__(256)
void addS_pack(const float* __restrict__ P, float* __restrict__ out,
               unsigned* __restrict__ hi, unsigned* __restrict__ lo,
               size_t n4, size_t str4, int S)
{
    size_t i = (size_t)blockIdx.x * 256 + threadIdx.x;
    if (i >= n4) return;
    const float4* p4 = reinterpret_cast<const float4*>(P);
    float4 a = p4[i];
    for (int s = 1; s < S; s++) {
        float4 b = p4[i + (size_t)s * str4];
        a.x += b.x; a.y += b.y; a.z += b.z; a.w += b.w;
    }
    reinterpret_cast<float4*>(out)[i] = a;
    if (hi) {
        float r0, r1, r2, r3;
        unsigned h0 = h_hi(a.x, r0), h1 = h_hi(a.y, r1);
        unsigned h2 = h_hi(a.z, r2), h3 = h_hi(a.w, r3);
        hi[2 * i]     = h0 | (h1 << 16);
        hi[2 * i + 1] = h2 | (h3 << 16);
        lo[2 * i]     = h_bits(r0) | (h_bits(r1) << 16);
        lo[2 * i + 1] = h_bits(r2) | (h_bits(r3) << 16);
    }
}

// ---------------------------------------------------------------------------
// split fp16 tensor GEMM, 3-stage pipeline, swizzled 64B smem rows.
// C[M,N] = A[M,K]*B[N,K]^T over K elems from pair offset koff
// (+ blockIdx.z*kqPairs split-K; output slice blockIdx.z*sliceElems).
// NMMA=3: hh+hl+lh.  NMMA=2: hh+lh (Blo unused).
// EPI 0: fp32 store. EPI 1: tanh(acc+aux[col]) -> transposed fp16 pairs Tt.
// EPI 2: 0.5*acc - aux[col].
// ---------------------------------------------------------------------------
#define BK 32
#define KPT 16
#define TILE_B 8192          // 128 rows * 64 B
#define NSTG 3
#define SM3 (NSTG * 4 * TILE_B)   // 96 KB
#define SM2 (NSTG * 3 * TILE_B)   // 72 KB

__device__ __forceinline__ void mma_f16(float* c, const unsigned* a, const unsigned* b)
{
    asm volatile(
        "mma.sync.aligned.m16n8k16.row.col.f32.f16.f16.f32 "
        "{%0,%1,%2,%3}, {%4,%5,%6,%7}, {%8,%9}, {%0,%1,%2,%3};"
        : "+f"(c[0]), "+f"(c[1]), "+f"(c[2]), "+f"(c[3])
        : "r"(a[0]), "r"(a[1]), "r"(a[2]), "r"(a[3]), "r"(b[0]), "r"(b[1]));
}
__device__ __forceinline__ void ldmx4(unsigned* r, unsigned a)
{
    asm volatile("ldmatrix.sync.aligned.m8n8.x4.shared.b16 {%0,%1,%2,%3}, [%4];"
                 : "=r"(r[0]), "=r"(r[1]), "=r"(r[2]), "=r"(r[3]) : "r"(a));
}
__device__ __forceinline__ void cpa16(unsigned dst, const void* src, bool pred)
{
    int sz = pred ? 16 : 0;
    asm volatile("cp.async.cg.shared.global [%0], [%1], 16, %2;\n"
                 :: "r"(dst), "l"(src), "r"(sz));
}

template <int NMMA, int EPI>
__global__ __launch_bounds__(256, 2)
void gemm6(const unsigned* __restrict__ Ahi, const unsigned* __restrict__ Alo,
           const unsigned* __restrict__ Bhi, const unsigned* __restrict__ Blo,
           const float* __restrict__ aux, float* __restrict__ C,
           unsigned* __restrict__ Tt,
           int M, int N, int K, int ldA, int ldB, int koff,
           int kqPairs, size_t sliceElems)
{
    extern __shared__ __align__(16) unsigned dynbuf[];
    const int NBUF = (NMMA == 3) ? 4 : 3;
    const int tid  = threadIdx.x;
    const int bm   = blockIdx.y * 128, bn = blockIdx.x * 128;
    const int lane = tid & 31, wid = tid >> 5;
    const int wr   = (wid >> 2) * 64, wc = (wid & 3) * 32;
    const int g    = lane >> 2, t = lane & 3;
    const int kp0base = koff + blockIdx.z * kqPairs;
    float* Cz = C + (size_t)blockIdx.z * sliceElems;

    float acc[4][4][4];
#pragma unroll
    for (int mi = 0; mi < 4; mi++)
#pragma unroll
        for (int ni = 0; ni < 4; ni++)
#pragma unroll
            for (int k = 0; k < 4; k++) acc[mi][ni][k] = 0.f;

    const int NIT = K / BK;
    const unsigned sbase = (unsigned)__cvta_generic_to_shared(dynbuf);
    // ldmatrix per-lane offsets (loop invariant; swizzle factor X = (rl>>1)&3)
    const unsigned rl = (unsigned)(lane & 15), jsel = (unsigned)(lane >> 4);
    const unsigned X = (rl >> 1) & 3;
    const unsigned moff0 = rl * 64 + (((0 + jsel) ^ X) << 4);
    const unsigned moff1 = rl * 64 + (((2 + jsel) ^ X) << 4);

    // cp.async per-thread store offsets (2 chunks per tile per thread)
    auto soff_of = [&](int c) {
        unsigned row = (unsigned)(c >> 2), j = (unsigned)(c & 3);
        return row * 64 + ((j ^ ((row >> 1) & 3)) << 4);
    };
    const unsigned so0 = soff_of(tid), so1 = soff_of(tid + 256);

    auto prefetch = [&](int it, int s) {
        const int kp0 = kp0base + it * KPT;
        const unsigned stg = sbase + (unsigned)(s * NBUF) * TILE_B;
#pragma unroll
        for (int h = 0; h < 2; h++) {
            int c = tid + h * 256;
            int row = c >> 2, seg = (c & 3) << 2;       // seg in u32 pairs
            unsigned soff = h ? so1 : so0;
            bool pa = (bm + row) < M;
            bool pb = (bn + row) < N;
            size_t ga = (size_t)(pa ? bm + row : 0) * ldA + kp0 + seg;
            size_t gb = (size_t)(pb ? bn + row : 0) * ldB + kp0 + seg;
            cpa16(stg + 0 * TILE_B + soff, Ahi + ga, pa);
            cpa16(stg + 1 * TILE_B + soff, Alo + ga, pa);
            cpa16(stg + 2 * TILE_B + soff, Bhi + gb, pb);
            if (NMMA == 3)
                cpa16(stg + 3 * TILE_B + soff, Blo + gb, pb);
        }
        asm volatile("cp.async.commit_group;\n");
    };

    prefetch(0, 0);
    prefetch(1, 1);

    for (int it = 0; it < NIT; ++it) {
        const int s = it % NSTG;
        if (it + 1 < NIT) asm volatile("cp.async.wait_group 1;\n");
        else              asm volatile("cp.async.wait_group 0;\n");
        __syncthreads();

        const unsigned sA_hi = sbase + (unsigned)(s * NBUF + 0) * TILE_B;
        const unsigned sA_lo = sbase + (unsigned)(s * NBUF + 1) * TILE_B;
        const unsigned sB_hi = sbase + (unsigned)(s * NBUF + 2) * TILE_B;
        const unsigned sB_lo = sbase + (unsigned)(s * NBUF + 3) * TILE_B;

#pragma unroll
        for (int ks = 0; ks < 2; ks++) {
            const unsigned mo = ks ? moff1 : moff0;
            unsigned ah[4][4], al[4][4], bh[4][2], bl[4][2];
#pragma unroll
            for (int mi = 0; mi < 4; mi++) {
                unsigned off = mo + (unsigned)((wr + mi * 16) * 64);
                ldmx4(ah[mi], sA_hi + off);
                ldmx4(al[mi], sA_lo + off);
            }
#pragma unroll
            for (int nj = 0; nj < 2; nj++) {
                unsigned off = mo + (unsigned)((wc + nj * 16) * 64);
                unsigned bt[4];
                ldmx4(bt, sB_hi + off);
                bh[2 * nj][0] = bt[0]; bh[2 * nj + 1][0] = bt[1];
                bh[2 * nj][1] = bt[2]; bh[2 * nj + 1][1] = bt[3];
                if (NMMA == 3) {
                    ldmx4(bt, sB_lo + off);
                    bl[2 * nj][0] = bt[0]; bl[2 * nj + 1][0] = bt[1];
                    bl[2 * nj][1] = bt[2]; bl[2 * nj + 1][1] = bt[3];
                }
            }
#pragma unroll
            for (int mi = 0; mi < 4; mi++)
#pragma unroll
                for (int ni = 0; ni < 4; ni++) {
                    mma_f16(acc[mi][ni], ah[mi], bh[ni]);
                    if (NMMA == 3) mma_f16(acc[mi][ni], ah[mi], bl[ni]);
                    mma_f16(acc[mi][ni], al[mi], bh[ni]);
                }
        }
        if (it + 2 < NIT) prefetch(it + 2, (it + 2) % NSTG);
    }

    if (EPI == 0 || EPI == 2) {
#pragma unroll
        for (int mi = 0; mi < 4; mi++) {
            int r = bm + wr + mi * 16 + g;
#pragma unroll
            for (int ni = 0; ni < 4; ni++) {
                int cc = bn + wc + ni * 8 + 2 * t;
                if (cc < N) {
                    float2 v0, v1;
                    if (EPI == 2) {
                        float a0 = aux[cc], a1 = aux[cc + 1];
                        v0 = make_float2(0.5f * acc[mi][ni][0] - a0,
                                         0.5f * acc[mi][ni][1] - a1);
                        v1 = make_float2(0.5f * acc[mi][ni][2] - a0,
                                         0.5f * acc[mi][ni][3] - a1);
                    } else {
                        v0 = make_float2(acc[mi][ni][0], acc[mi][ni][1]);
                        v1 = make_float2(acc[mi][ni][2], acc[mi][ni][3]);
                    }
                    if (r < M)
                        *reinterpret_cast<float2*>(&Cz[(size_t)r * N + cc]) = v0;
                    if (r + 8 < M)
                        *reinterpret_cast<float2*>(&Cz[(size_t)(r + 8) * N + cc]) = v1;
                }
            }
        }
    } else {
        const size_t Mh = (size_t)(M >> 1);
#pragma unroll
        for (int mi = 0; mi < 4; mi++) {
            int mglob = bm + wr + mi * 16 + g;
#pragma unroll
            for (int ni = 0; ni < 4; ni++) {
                int cc = bn + wc + ni * 8 + 2 * t;
                float b0 = aux[cc], b1 = aux[cc + 1];
                float v[4];
                v[0] = fast_tanh(acc[mi][ni][0] + b0);
                v[1] = fast_tanh(acc[mi][ni][1] + b1);
                v[2] = fast_tanh(acc[mi][ni][2] + b0);
                v[3] = fast_tanh(acc[mi][ni][3] + b1);
#pragma unroll
                for (int vi = 0; vi < 4; vi++) {
                    unsigned hb = h_bits(v[vi]);
                    unsigned oth = __shfl_xor_sync(0xffffffffu, hb, 4);
                    if ((lane & 4) == 0) {
                        int n = cc + (vi & 1);
                        int mp = ((mglob + ((vi >> 1) << 3)) >> 1);
                        Tt[(size_t)n * Mh + mp] = hb | (oth << 16);
                    }
                }
            }
        }
    }
}

// ---------------------------------------------------------------------------
// Host orchestration
// ---------------------------------------------------------------------------
static void run_level(const float* h_fp32, bool need_pack_h,
                      unsigned* hPhi, unsigned* hPlo,
                      const float* centers, const float* W, const float* b,
                      int n_prev, int n_cur,
                      unsigned* cPhi, unsigned* cPlo, unsigned* wPhi,
                      float* G, float* cnq,
                      unsigned* GThi, unsigned* GTlo, unsigned* tT,
                      float* out, unsigned* outPhi, unsigned* outPlo)
{
    const int ldD = D / 2;
    if (need_pack_h) {
        size_t np = (size_t)n_prev * (D / 2);
        pack_pair<<<(unsigned)((np + 255) / 256), 256>>>(h_fp32, hPhi, hPlo, np);
    }
    pack_c<<<n_cur, 256>>>(centers, cPhi, cPlo, cnq, D / 2);
    {
        size_t np = (size_t)D * (D / 2);
        pack_hi_only<<<(unsigned)((np + 255) / 256), 256>>>(W, wPhi, np);
    }
    // logits = 0.5*h@c^T - cnq  (3-term)
    {
        dim3 grid((n_cur + 127) / 128, (n_prev + 127) / 128, 1);
        gemm6<3, 2><<<grid, 256, SM3>>>(hPhi, hPlo, cPhi, cPlo, cnq, G, nullptr,
                                        n_prev, n_cur, D, ldD, ldD, 0, 0, 0);
    }
    softmax_transpose<<<n_prev / 32, 256>>>(G, GThi, GTlo, n_prev, n_cur);
    // t = tanh(h@W^T + b) -> transposed fp16 pairs (2-term)
    {
        dim3 grid(D / 128, n_prev / 128, 1);
        gemm6<2, 1><<<grid, 256, SM2>>>(hPhi, hPlo, wPhi, nullptr, b, nullptr, tT,
                                        n_prev, D, D, ldD, ldD, 0, 0, 0);
    }
    // out = p^T @ t  (2-term), split-K=4 via gridDim.z
    {
        const int S = 4;
        const int ldK = n_prev / 2;
        const int Ks = n_prev / S;
        dim3 grid(D / 128, (n_cur + 127) / 128, S);
        gemm6<2, 0><<<grid, 256, SM2>>>(GThi, GTlo, tT, nullptr, nullptr, G, nullptr,
                                        n_cur, D, Ks, ldK, ldK, 0,
                                        Ks / 2, (size_t)n_cur * D);
        size_t n4 = (size_t)n_cur * D / 4;
        addS_pack<<<(unsigned)((n4 + 255) / 256), 256>>>(G, out, outPhi, outPlo,
                                                         n4, n4, S);
    }
}

extern "C" void kernel_launch(void* const* d_in, const int* in_sizes, int n_in,
                              void* d_out, int out_size)
{
    const float* h0 = (const float*)d_in[0];
    const float* c1 = (const float*)d_in[1];
    const float* c2 = (const float*)d_in[2];
    const float* c3 = (const float*)d_in[3];
    const float* W1 = (const float*)d_in[4];
    const float* b1 = (const float*)d_in[5];
    const float* W2 = (const float*)d_in[6];
    const float* b2 = (const float*)d_in[7];
    const float* W3 = (const float*)d_in[8];
    const float* b3 = (const float*)d_in[9];
    float* out = (float*)d_out;

    cudaFuncSetAttribute(gemm6<3, 2>, cudaFuncAttributeMaxDynamicSharedMemorySize, SM3);
    cudaFuncSetAttribute(gemm6<2, 1>, cudaFuncAttributeMaxDynamicSharedMemorySize, SM2);
    cudaFuncSetAttribute(gemm6<2, 0>, cudaFuncAttributeMaxDynamicSharedMemorySize, SM2);

    float *pG, *pcnq, *pHn;
    unsigned *hPhi, *hPlo, *cPhi, *cPlo, *wPhi, *GThi, *GTlo, *tT;
    cudaGetSymbolAddress((void**)&pG,   g_G);
    cudaGetSymbolAddress((void**)&pcnq, g_cnq);
    cudaGetSymbolAddress((void**)&pHn,  g_Hn);
    cudaGetSymbolAddress((void**)&hPhi, g_hPhi);
    cudaGetSymbolAddress((void**)&hPlo, g_hPlo);
    cudaGetSymbolAddress((void**)&cPhi, g_cPhi);
    cudaGetSymbolAddress((void**)&cPlo, g_cPlo);
    cudaGetSymbolAddress((void**)&wPhi, g_wPhi);
    cudaGetSymbolAddress((void**)&GThi, g_GThi);
    cudaGetSymbolAddress((void**)&GTlo, g_GTlo);
    cudaGetSymbolAddress((void**)&tT,   g_tT);

    run_level(h0, true, hPhi, hPlo, c1, W1, b1, N0, N1,
              cPhi, cPlo, wPhi, pG, pcnq, GThi, GTlo, tT, pHn, hPhi, hPlo);
    run_level(pHn, false, hPhi, hPlo, c2, W2, b2, N1, N2,
              cPhi, cPlo, wPhi, pG, pcnq, GThi, GTlo, tT, pHn, hPhi, hPlo);
    run_level(pHn, false, hPhi, hPlo, c3, W3, b3, N2, N3,
              cPhi, cPlo, wPhi, pG, pcnq, GThi, GTlo, tT, out, nullptr, nullptr);
}